// round 13
// baseline (speedup 1.0000x reference)
#include <cuda_runtime.h>
#include <cstdint>
#include <cstddef>

#define TSIZE (1u << 18)
#define TMASK (TSIZE - 1u)
#define NLEV 16
#define P1 2654435761u
#define P2 805459861u

#define NBUCK (1u << 18)   // 64^3 buckets, Morton-coded (proven best)
#define NMAX (1 << 21)
#define CAP 2400           // smem tile capacity (float2 entries)

__constant__ int c_res[NLEV] = {16, 20, 25, 32, 40, 50, 64, 80,
                                101, 128, 161, 203, 256, 322, 406, 512};

// Device-global scratch (no allocation).
// g_count zero at module load; scan re-zeroes after consuming -> zero at the
// start of every kernel_launch invocation (incl. graph replays).
__device__ __align__(16) float2 g_hash[15u * TSIZE];
__device__ __align__(16) float2 g_dense[16 * 16 * 16];
__device__ unsigned g_count[NBUCK];
__device__ unsigned g_cursor[NBUCK];
__device__ unsigned g_total;
__device__ float4   g_buf[NMAX];           // bucketed points {x,y,z,idx}

__device__ __forceinline__ unsigned expand3(unsigned v) {
    v &= 0x3Fu;
    v = (v | (v << 8)) & 0x0300F00Fu;
    v = (v | (v << 4)) & 0x030C30C3u;
    v = (v | (v << 2)) & 0x09249249u;
    return v;
}

__device__ __forceinline__ int bucket_of(float cx, float cy, float cz) {
    unsigned bx = (unsigned)min(63, max(0, (int)((cx + 1.0f) * 32.0f)));
    unsigned by = (unsigned)min(63, max(0, (int)((cy + 1.0f) * 32.0f)));
    unsigned bz = (unsigned)min(63, max(0, (int)((cz + 1.0f) * 32.0f)));
    return (int)(expand3(bx) | (expand3(by) << 1) | (expand3(bz) << 2));
}

// ---------------------------------------------------------------------------
// Repack (stream B).
// ---------------------------------------------------------------------------
__global__ void repack_kernel(const float* __restrict__ dense,
                              const float* __restrict__ hash) {
    unsigned i = blockIdx.x * blockDim.x + threadIdx.x;
    if (i < 15u * TSIZE / 2u) {
        unsigned l = i / (TSIZE / 2u);
        unsigned t = (i % (TSIZE / 2u)) * 2u;
        const float* base = hash + (size_t)l * (2u * TSIZE);
        const float2 lo = *reinterpret_cast<const float2*>(base + t);
        const float2 hi = *reinterpret_cast<const float2*>(base + TSIZE + t);
        float4 v = make_float4(lo.x, hi.x, lo.y, hi.y);
        *reinterpret_cast<float4*>(&g_hash[l * TSIZE + t]) = v;
    }
    if (i < 4096u)
        g_dense[i] = make_float2(dense[i], dense[4096u + i]);
}

__global__ void hist_kernel(const float* __restrict__ coords, int N) {
    int i = blockIdx.x * blockDim.x + threadIdx.x;
    if (i == 0) g_total = 0u;
    if (i >= N) return;
    int b = bucket_of(coords[3 * i], coords[3 * i + 1], coords[3 * i + 2]);
    atomicAdd(&g_count[b], 1u);
}

__global__ __launch_bounds__(1024)
void scan_kernel() {
    __shared__ unsigned sh[1024];
    __shared__ unsigned base;
    const int b = blockIdx.x, t = threadIdx.x;
    const unsigned gi = b * 1024 + t;
    const unsigned v = g_count[gi];
    g_count[gi] = 0u;                       // self-clean for next invocation
    sh[t] = v;
    __syncthreads();
    for (int off = 1; off < 1024; off <<= 1) {
        unsigned u = 0;
        if (t >= off) u = sh[t - off];
        __syncthreads();
        sh[t] += u;
        __syncthreads();
    }
    if (t == 1023) base = atomicAdd(&g_total, sh[1023]);
    __syncthreads();
    g_cursor[gi] = base + sh[t] - v;
}

__global__ void scatter_kernel(const float* __restrict__ coords, int N) {
    int i = blockIdx.x * blockDim.x + threadIdx.x;
    if (i >= N) return;
    float x = coords[3 * i], y = coords[3 * i + 1], z = coords[3 * i + 2];
    int b = bucket_of(x, y, z);
    unsigned slot = atomicAdd(&g_cursor[b], 1u);
    g_buf[slot] = make_float4(x, y, z, __int_as_float(i));
}

// ---------------------------------------------------------------------------
// Encode: Morton-ordered points; levels 1..11 use CTA-cooperative smem tiles
// (bbox gather once per CTA), level 0 dense tiled too; levels 12..15 direct.
// ---------------------------------------------------------------------------
__global__ __launch_bounds__(256, 6)
void encode_kernel(float* __restrict__ out, int N) {
    __shared__ float2 tile[CAP];
    __shared__ float rmn[3][8], rmx[3][8];

    const int tid = threadIdx.x;
    const int i = blockIdx.x * 256 + tid;
    const int ii = min(i, N - 1);

    const float4 pt = g_buf[ii];
    const float cx = pt.x, cy = pt.y, cz = pt.z;
    const int idx = __float_as_int(pt.w);
    float4* __restrict__ out4 = reinterpret_cast<float4*>(out + (size_t)idx * 32);

    // Block-wide min/max of coords (warp shuffle + smem).
    float mn[3] = {cx, cy, cz}, mx[3] = {cx, cy, cz};
#pragma unroll
    for (int off = 16; off > 0; off >>= 1) {
#pragma unroll
        for (int d = 0; d < 3; ++d) {
            mn[d] = fminf(mn[d], __shfl_xor_sync(0xFFFFFFFFu, mn[d], off));
            mx[d] = fmaxf(mx[d], __shfl_xor_sync(0xFFFFFFFFu, mx[d], off));
        }
    }
    const int wid = tid >> 5;
    if ((tid & 31) == 0) {
#pragma unroll
        for (int d = 0; d < 3; ++d) { rmn[d][wid] = mn[d]; rmx[d][wid] = mx[d]; }
    }
    __syncthreads();
    float bmn[3], bmx[3];
#pragma unroll
    for (int d = 0; d < 3; ++d) {
        bmn[d] = rmn[d][0]; bmx[d] = rmx[d][0];
#pragma unroll
        for (int w = 1; w < 8; ++w) {
            bmn[d] = fminf(bmn[d], rmn[d][w]);
            bmx[d] = fmaxf(bmx[d], rmx[d][w]);
        }
    }

    float4 obuf = make_float4(0.f, 0.f, 0.f, 0.f);

    // ---- Levels 0..11: tiled (runtime loop keeps code size down) ----
    for (int l = 0; l < 12; ++l) {
        const int res = c_res[l];
        const float rm1 = (float)(res - 1);

        float px = fminf(fmaxf((cx + 1.0f) * 0.5f * rm1, 0.0f), rm1);
        float py = fminf(fmaxf((cy + 1.0f) * 0.5f * rm1, 0.0f), rm1);
        float pz = fminf(fmaxf((cz + 1.0f) * 0.5f * rm1, 0.0f), rm1);
        int ix0 = (int)px;  float wx = px - (float)ix0;
        int iy0 = (int)py;  float wy = py - (float)iy0;
        int iz0 = (int)pz;  float wz = pz - (float)iz0;
        int ix1 = min(ix0 + 1, res - 1);
        int iy1 = min(iy0 + 1, res - 1);
        int iz1 = min(iz0 + 1, res - 1);
        const float wxv0 = 1.0f - wx, wxv1 = wx;
        const float wyv0 = 1.0f - wy, wyv1 = wy;
        const float wzv0 = 1.0f - wz, wzv1 = wz;

        // Block bbox at this level (uniform across CTA: derived from reduction).
        const int ilx = (int)fminf(fmaxf((bmn[0] + 1.0f) * 0.5f * rm1, 0.0f), rm1);
        const int ily = (int)fminf(fmaxf((bmn[1] + 1.0f) * 0.5f * rm1, 0.0f), rm1);
        const int ilz = (int)fminf(fmaxf((bmn[2] + 1.0f) * 0.5f * rm1, 0.0f), rm1);
        const int ihx = (int)fminf(fmaxf((bmx[0] + 1.0f) * 0.5f * rm1, 0.0f), rm1);
        const int ihy = (int)fminf(fmaxf((bmx[1] + 1.0f) * 0.5f * rm1, 0.0f), rm1);
        const int ihz = (int)fminf(fmaxf((bmx[2] + 1.0f) * 0.5f * rm1, 0.0f), rm1);
        const int nx = ihx - ilx + 2;
        const int ny = ihy - ily + 2;
        const int nz = ihz - ilz + 2;
        const int nv = nx * ny * nz;

        float a0 = 0.0f, a1 = 0.0f;

        if (nv <= CAP) {
            __syncthreads();               // previous level done with tile
            if (l == 0) {
                for (int j = tid; j < nv; j += 256) {
                    int dz = j % nz; int t2 = j / nz;
                    int dy = t2 % ny; int dx = t2 / ny;
                    int gx = min(ilx + dx, 15);
                    int gy = min(ily + dy, 15);
                    int gz = min(ilz + dz, 15);
                    tile[j] = g_dense[(gx * 16 + gy) * 16 + gz];
                }
            } else {
                const float2* __restrict__ tbl = g_hash + (size_t)(l - 1) * TSIZE;
                for (int j = tid; j < nv; j += 256) {
                    int dz = j % nz; int t2 = j / nz;
                    int dy = t2 % ny; int dx = t2 / ny;
                    unsigned h = ((unsigned)(ilx + dx) ^
                                  (unsigned)(ily + dy) * P1 ^
                                  (unsigned)(ilz + dz) * P2) & TMASK;
                    tile[j] = __ldg(&tbl[h]);
                }
            }
            __syncthreads();

            const int lx0 = ix0 - ilx, lx1 = ix1 - ilx;
            const int ly0 = iy0 - ily, ly1 = iy1 - ily;
            const int lz0 = iz0 - ilz, lz1 = iz1 - ilz;
#pragma unroll
            for (int c = 0; c < 8; ++c) {
                const int lx = (c & 4) ? lx1 : lx0;
                const int ly = (c & 2) ? ly1 : ly0;
                const int lz = (c & 1) ? lz1 : lz0;
                const float2 f = tile[(lx * ny + ly) * nz + lz];
                const float w = ((c & 4) ? wxv1 : wxv0) *
                                ((c & 2) ? wyv1 : wyv0) *
                                ((c & 1) ? wzv1 : wzv0);
                a0 = fmaf(f.x, w, a0);
                a1 = fmaf(f.y, w, a1);
            }
        } else {
            // Fallback: direct gathers (rare Morton-discontinuity CTAs).
            if (l == 0) {
#pragma unroll
                for (int c = 0; c < 8; ++c) {
                    const int xi = (c & 4) ? ix1 : ix0;
                    const int yi = (c & 2) ? iy1 : iy0;
                    const int zi = (c & 1) ? iz1 : iz0;
                    const float2 f = __ldg(&g_dense[(xi * 16 + yi) * 16 + zi]);
                    const float w = ((c & 4) ? wxv1 : wxv0) *
                                    ((c & 2) ? wyv1 : wyv0) *
                                    ((c & 1) ? wzv1 : wzv0);
                    a0 = fmaf(f.x, w, a0);
                    a1 = fmaf(f.y, w, a1);
                }
            } else {
                const float2* __restrict__ tbl = g_hash + (size_t)(l - 1) * TSIZE;
                const unsigned hx0 = (unsigned)ix0, hx1 = (unsigned)ix1;
                const unsigned hy0 = (unsigned)iy0 * P1, hy1 = (unsigned)iy1 * P1;
                const unsigned hz0 = (unsigned)iz0 * P2, hz1 = (unsigned)iz1 * P2;
#pragma unroll
                for (int c = 0; c < 8; ++c) {
                    const unsigned h = (((c & 4) ? hx1 : hx0) ^
                                        ((c & 2) ? hy1 : hy0) ^
                                        ((c & 1) ? hz1 : hz0)) & TMASK;
                    const float2 f = __ldg(&tbl[h]);
                    const float w = ((c & 4) ? wxv1 : wxv0) *
                                    ((c & 2) ? wyv1 : wyv0) *
                                    ((c & 1) ? wzv1 : wzv0);
                    a0 = fmaf(f.x, w, a0);
                    a1 = fmaf(f.y, w, a1);
                }
            }
        }

        if ((l & 1) == 0) {
            obuf.x = a0; obuf.y = a1;
        } else {
            obuf.z = a0; obuf.w = a1;
            if (i < N) out4[l >> 1] = obuf;
        }
    }

    // ---- Levels 12..15: direct gathers (no ordering/tiling can help) ----
    constexpr int RESF[4] = {256, 322, 406, 512};
#pragma unroll
    for (int k = 0; k < 4; ++k) {
        const int res = RESF[k];
        const float rm1 = (float)(res - 1);
        float px = fminf(fmaxf((cx + 1.0f) * 0.5f * rm1, 0.0f), rm1);
        float py = fminf(fmaxf((cy + 1.0f) * 0.5f * rm1, 0.0f), rm1);
        float pz = fminf(fmaxf((cz + 1.0f) * 0.5f * rm1, 0.0f), rm1);
        int ix0 = (int)px;  float wx = px - (float)ix0;
        int iy0 = (int)py;  float wy = py - (float)iy0;
        int iz0 = (int)pz;  float wz = pz - (float)iz0;
        int ix1 = min(ix0 + 1, res - 1);
        int iy1 = min(iy0 + 1, res - 1);
        int iz1 = min(iz0 + 1, res - 1);
        const float wxv0 = 1.0f - wx, wxv1 = wx;
        const float wyv0 = 1.0f - wy, wyv1 = wy;
        const float wzv0 = 1.0f - wz, wzv1 = wz;

        const float2* __restrict__ tbl = g_hash + (size_t)(k + 11) * TSIZE;
        const unsigned hx0 = (unsigned)ix0, hx1 = (unsigned)ix1;
        const unsigned hy0 = (unsigned)iy0 * P1, hy1 = (unsigned)iy1 * P1;
        const unsigned hz0 = (unsigned)iz0 * P2, hz1 = (unsigned)iz1 * P2;

        float a0 = 0.0f, a1 = 0.0f;
#pragma unroll
        for (int c = 0; c < 8; ++c) {
            const unsigned h = (((c & 4) ? hx1 : hx0) ^
                                ((c & 2) ? hy1 : hy0) ^
                                ((c & 1) ? hz1 : hz0)) & TMASK;
            const float2 f = __ldg(&tbl[h]);
            const float w = ((c & 4) ? wxv1 : wxv0) *
                            ((c & 2) ? wyv1 : wyv0) *
                            ((c & 1) ? wzv1 : wzv0);
            a0 = fmaf(f.x, w, a0);
            a1 = fmaf(f.y, w, a1);
        }

        if ((k & 1) == 0) {
            obuf.x = a0; obuf.y = a1;
        } else {
            obuf.z = a0; obuf.w = a1;
            if (i < N) out4[6 + (k >> 1)] = obuf;
        }
    }
}

// ---------------------------------------------------------------------------
// kernel_launch:
//   stream 0: hist -> scan -> scatter -> encode
//   stream B: repack (independent, joins before encode)
// ---------------------------------------------------------------------------
extern "C" void kernel_launch(void* const* d_in, const int* in_sizes, int n_in,
                              void* d_out, int out_size) {
    const float* coords = (const float*)d_in[0];
    const float* dense  = (const float*)d_in[1];
    const float* hash   = (const float*)d_in[2];
    float* out = (float*)d_out;

    const int N = in_sizes[0] / 3;
    const int nb = (N + 255) / 256;

    static cudaStream_t s_b = nullptr;
    static cudaEvent_t ev_start = nullptr, ev_repack = nullptr;
    if (s_b == nullptr) {
        cudaStreamCreateWithFlags(&s_b, cudaStreamNonBlocking);
        cudaEventCreateWithFlags(&ev_start, cudaEventDisableTiming);
        cudaEventCreateWithFlags(&ev_repack, cudaEventDisableTiming);
    }

    cudaEventRecord(ev_start, 0);
    cudaStreamWaitEvent(s_b, ev_start, 0);
    const unsigned repack_threads = 15u * TSIZE / 2u;
    repack_kernel<<<(repack_threads + 255u) / 256u, 256, 0, s_b>>>(dense, hash);
    cudaEventRecord(ev_repack, s_b);

    hist_kernel<<<nb, 256>>>(coords, N);
    scan_kernel<<<NBUCK / 1024, 1024>>>();
    scatter_kernel<<<nb, 256>>>(coords, N);

    cudaStreamWaitEvent(0, ev_repack, 0);
    encode_kernel<<<nb, 256>>>(out, N);
}

// round 14
// speedup vs baseline: 1.2300x; 1.2300x over previous
#include <cuda_runtime.h>
#include <cstdint>
#include <cstddef>

#define TSIZE (1u << 18)
#define TMASK (TSIZE - 1u)
#define NLEV 16
#define P1 2654435761u
#define P2 805459861u

#define NBUCK (1u << 18)   // 64^3 buckets, Morton-coded (proven best)
#define NMAX (1 << 21)

// Device-global scratch (no allocation).
// g_count zero at module load; scan re-zeroes after consuming -> zero at the
// start of every kernel_launch invocation (incl. graph replays).
__device__ __align__(16) float2 g_hash[15u * TSIZE];
__device__ __align__(16) float2 g_dense[16 * 16 * 16];
__device__ unsigned g_count[NBUCK];
__device__ unsigned g_cursor[NBUCK];
__device__ unsigned g_total;
__device__ float4   g_buf[NMAX];           // bucketed points {x,y,z,idx}

__device__ __forceinline__ unsigned expand3(unsigned v) {
    v &= 0x3Fu;
    v = (v | (v << 8)) & 0x0300F00Fu;
    v = (v | (v << 4)) & 0x030C30C3u;
    v = (v | (v << 2)) & 0x09249249u;
    return v;
}

__device__ __forceinline__ int bucket_of(float cx, float cy, float cz) {
    unsigned bx = (unsigned)min(63, max(0, (int)((cx + 1.0f) * 32.0f)));
    unsigned by = (unsigned)min(63, max(0, (int)((cy + 1.0f) * 32.0f)));
    unsigned bz = (unsigned)min(63, max(0, (int)((cz + 1.0f) * 32.0f)));
    return (int)(expand3(bx) | (expand3(by) << 1) | (expand3(bz) << 2));
}

// ---------------------------------------------------------------------------
// Repack (stream B): tables -> feature-interleaved float2. 2 entries/thread.
// ---------------------------------------------------------------------------
__global__ void repack_kernel(const float* __restrict__ dense,
                              const float* __restrict__ hash) {
    unsigned i = blockIdx.x * blockDim.x + threadIdx.x;
    if (i < 15u * TSIZE / 2u) {
        unsigned l = i / (TSIZE / 2u);
        unsigned t = (i % (TSIZE / 2u)) * 2u;
        const float* base = hash + (size_t)l * (2u * TSIZE);
        const float2 lo = *reinterpret_cast<const float2*>(base + t);
        const float2 hi = *reinterpret_cast<const float2*>(base + TSIZE + t);
        float4 v = make_float4(lo.x, hi.x, lo.y, hi.y);
        *reinterpret_cast<float4*>(&g_hash[l * TSIZE + t]) = v;
    }
    if (i < 4096u)
        g_dense[i] = make_float2(dense[i], dense[4096u + i]);
}

// ---------------------------------------------------------------------------
// Histogram: 4 points/thread via 3x LDG.128. Resets g_total for the scan.
// ---------------------------------------------------------------------------
__global__ void hist_kernel(const float* __restrict__ coords, int N) {
    int j = blockIdx.x * blockDim.x + threadIdx.x;   // quad index
    if (j == 0) g_total = 0u;
    int p0 = j * 4;
    if (p0 >= N) return;
    if (p0 + 4 <= N) {
        const float4* c4 = reinterpret_cast<const float4*>(coords + (size_t)p0 * 3);
        const float4 a = __ldg(c4 + 0);
        const float4 b = __ldg(c4 + 1);
        const float4 c = __ldg(c4 + 2);
        atomicAdd(&g_count[bucket_of(a.x, a.y, a.z)], 1u);
        atomicAdd(&g_count[bucket_of(a.w, b.x, b.y)], 1u);
        atomicAdd(&g_count[bucket_of(b.z, b.w, c.x)], 1u);
        atomicAdd(&g_count[bucket_of(c.y, c.z, c.w)], 1u);
    } else {
        for (int p = p0; p < N; ++p) {
            int b = bucket_of(coords[3 * p], coords[3 * p + 1], coords[3 * p + 2]);
            atomicAdd(&g_count[b], 1u);
        }
    }
}

// ---------------------------------------------------------------------------
// Single-kernel scan: per-block scan + atomic global base (self-cleaning).
// ---------------------------------------------------------------------------
__global__ __launch_bounds__(1024)
void scan_kernel() {
    __shared__ unsigned sh[1024];
    __shared__ unsigned base;
    const int b = blockIdx.x, t = threadIdx.x;
    const unsigned gi = b * 1024 + t;
    const unsigned v = g_count[gi];
    g_count[gi] = 0u;                       // self-clean for next invocation
    sh[t] = v;
    __syncthreads();
    for (int off = 1; off < 1024; off <<= 1) {
        unsigned u = 0;
        if (t >= off) u = sh[t - off];
        __syncthreads();
        sh[t] += u;
        __syncthreads();
    }
    if (t == 1023) base = atomicAdd(&g_total, sh[1023]);
    __syncthreads();
    g_cursor[gi] = base + sh[t] - v;        // global exclusive prefix
}

// ---------------------------------------------------------------------------
// Scatter: 4 points/thread via 3x LDG.128.
// ---------------------------------------------------------------------------
__global__ void scatter_kernel(const float* __restrict__ coords, int N) {
    int j = blockIdx.x * blockDim.x + threadIdx.x;
    int p0 = j * 4;
    if (p0 >= N) return;
    if (p0 + 4 <= N) {
        const float4* c4 = reinterpret_cast<const float4*>(coords + (size_t)p0 * 3);
        const float4 a = __ldg(c4 + 0);
        const float4 b = __ldg(c4 + 1);
        const float4 c = __ldg(c4 + 2);
        float xs[4] = {a.x, a.w, b.z, c.y};
        float ys[4] = {a.y, b.x, b.w, c.z};
        float zs[4] = {a.z, b.y, c.x, c.w};
#pragma unroll
        for (int k = 0; k < 4; ++k) {
            int bk = bucket_of(xs[k], ys[k], zs[k]);
            unsigned slot = atomicAdd(&g_cursor[bk], 1u);
            g_buf[slot] = make_float4(xs[k], ys[k], zs[k],
                                      __int_as_float(p0 + k));
        }
    } else {
        for (int p = p0; p < N; ++p) {
            float x = coords[3 * p], y = coords[3 * p + 1], z = coords[3 * p + 2];
            int b = bucket_of(x, y, z);
            unsigned slot = atomicAdd(&g_cursor[b], 1u);
            g_buf[slot] = make_float4(x, y, z, __int_as_float(p));
        }
    }
}

// ---------------------------------------------------------------------------
// Encode: proven R11 body, Morton 64^3 bucket order, all 16 levels.
// ---------------------------------------------------------------------------
__global__ __launch_bounds__(256)
void encode_kernel(float* __restrict__ out, int N) {
    int i = blockIdx.x * blockDim.x + threadIdx.x;
    if (i >= N) return;

    const float4 pt = g_buf[i];
    const float cx = pt.x, cy = pt.y, cz = pt.z;
    const int idx = __float_as_int(pt.w);

    float4* __restrict__ out4 = reinterpret_cast<float4*>(out + (size_t)idx * 32);

    constexpr int RES[NLEV] = {16, 20, 25, 32, 40, 50, 64, 80,
                               101, 128, 161, 203, 256, 322, 406, 512};

    float4 obuf = make_float4(0.f, 0.f, 0.f, 0.f);

#pragma unroll
    for (int l = 0; l < NLEV; ++l) {
        const int res = RES[l];
        const float rm1 = (float)(res - 1);

        float px = fminf(fmaxf((cx + 1.0f) * 0.5f * rm1, 0.0f), rm1);
        float py = fminf(fmaxf((cy + 1.0f) * 0.5f * rm1, 0.0f), rm1);
        float pz = fminf(fmaxf((cz + 1.0f) * 0.5f * rm1, 0.0f), rm1);

        int ix0 = (int)px;  float wx = px - (float)ix0;
        int iy0 = (int)py;  float wy = py - (float)iy0;
        int iz0 = (int)pz;  float wz = pz - (float)iz0;
        int ix1 = min(ix0 + 1, res - 1);
        int iy1 = min(iy0 + 1, res - 1);
        int iz1 = min(iz0 + 1, res - 1);

        const float wxv0 = 1.0f - wx, wxv1 = wx;
        const float wyv0 = 1.0f - wy, wyv1 = wy;
        const float wzv0 = 1.0f - wz, wzv1 = wz;

        float2 f[8];
        float  wg[8];

        if (l == 0) {
#pragma unroll
            for (int c = 0; c < 8; ++c) {
                const int xi = (c & 4) ? ix1 : ix0;
                const int yi = (c & 2) ? iy1 : iy0;
                const int zi = (c & 1) ? iz1 : iz0;
                f[c] = __ldg(&g_dense[(xi * 16 + yi) * 16 + zi]);
                wg[c] = ((c & 4) ? wxv1 : wxv0) *
                        ((c & 2) ? wyv1 : wyv0) *
                        ((c & 1) ? wzv1 : wzv0);
            }
        } else {
            const float2* __restrict__ tbl = g_hash + (size_t)(l - 1) * TSIZE;
            const unsigned hx0 = (unsigned)ix0;  // prime 1
            const unsigned hx1 = (unsigned)ix1;
            const unsigned hy0 = (unsigned)iy0 * P1;
            const unsigned hy1 = (unsigned)iy1 * P1;
            const unsigned hz0 = (unsigned)iz0 * P2;
            const unsigned hz1 = (unsigned)iz1 * P2;
#pragma unroll
            for (int c = 0; c < 8; ++c) {
                const unsigned h = (((c & 4) ? hx1 : hx0) ^
                                    ((c & 2) ? hy1 : hy0) ^
                                    ((c & 1) ? hz1 : hz0)) & TMASK;
                f[c] = __ldg(&tbl[h]);
                wg[c] = ((c & 4) ? wxv1 : wxv0) *
                        ((c & 2) ? wyv1 : wyv0) *
                        ((c & 1) ? wzv1 : wzv0);
            }
        }

        float a0 = 0.0f, a1 = 0.0f;
#pragma unroll
        for (int c = 0; c < 8; ++c) {
            a0 = fmaf(f[c].x, wg[c], a0);
            a1 = fmaf(f[c].y, wg[c], a1);
        }

        if ((l & 1) == 0) {
            obuf.x = a0; obuf.y = a1;
        } else {
            obuf.z = a0; obuf.w = a1;
            out4[l >> 1] = obuf;
        }
    }
}

// ---------------------------------------------------------------------------
// kernel_launch:
//   stream 0: hist -> scan -> scatter -> encode
//   stream B: repack (independent, joins before encode)
// ---------------------------------------------------------------------------
extern "C" void kernel_launch(void* const* d_in, const int* in_sizes, int n_in,
                              void* d_out, int out_size) {
    const float* coords = (const float*)d_in[0];
    const float* dense  = (const float*)d_in[1];
    const float* hash   = (const float*)d_in[2];
    float* out = (float*)d_out;

    const int N = in_sizes[0] / 3;
    const int nb = (N + 255) / 256;
    const int nq = ((N + 3) / 4 + 255) / 256;   // quads

    static cudaStream_t s_b = nullptr;
    static cudaEvent_t ev_start = nullptr, ev_repack = nullptr;
    if (s_b == nullptr) {
        cudaStreamCreateWithFlags(&s_b, cudaStreamNonBlocking);
        cudaEventCreateWithFlags(&ev_start, cudaEventDisableTiming);
        cudaEventCreateWithFlags(&ev_repack, cudaEventDisableTiming);
    }

    cudaEventRecord(ev_start, 0);
    cudaStreamWaitEvent(s_b, ev_start, 0);
    const unsigned repack_threads = 15u * TSIZE / 2u;
    repack_kernel<<<(repack_threads + 255u) / 256u, 256, 0, s_b>>>(dense, hash);
    cudaEventRecord(ev_repack, s_b);

    hist_kernel<<<nq, 256>>>(coords, N);
    scan_kernel<<<NBUCK / 1024, 1024>>>();
    scatter_kernel<<<nq, 256>>>(coords, N);

    cudaStreamWaitEvent(0, ev_repack, 0);
    encode_kernel<<<nb, 256>>>(out, N);
}

// round 16
// speedup vs baseline: 1.2301x; 1.0001x over previous
#include <cuda_runtime.h>
#include <cstdint>
#include <cstddef>

#define TSIZE (1u << 18)
#define TMASK (TSIZE - 1u)
#define NLEV 16
#define P1 2654435761u
#define P2 805459861u

#define NBUCK (1u << 18)   // 64^3 buckets, Morton-coded (proven best)
#define NMAX (1 << 21)

// Device-global scratch (no allocation).
// g_count zero at module load; scan re-zeroes after consuming -> zero at the
// start of every kernel_launch invocation (incl. graph replays).
__device__ __align__(16) float2 g_hash[15u * TSIZE];
__device__ __align__(16) float2 g_dense[16 * 16 * 16];
__device__ unsigned g_count[NBUCK];
__device__ unsigned g_cursor[NBUCK];
__device__ unsigned g_total;
__device__ float4   g_buf[NMAX];           // bucketed points {x,y,z,idx}

__device__ __forceinline__ unsigned expand3(unsigned v) {
    v &= 0x3Fu;
    v = (v | (v << 8)) & 0x0300F00Fu;
    v = (v | (v << 4)) & 0x030C30C3u;
    v = (v | (v << 2)) & 0x09249249u;
    return v;
}

__device__ __forceinline__ int bucket_of(float cx, float cy, float cz) {
    unsigned bx = (unsigned)min(63, max(0, (int)((cx + 1.0f) * 32.0f)));
    unsigned by = (unsigned)min(63, max(0, (int)((cy + 1.0f) * 32.0f)));
    unsigned bz = (unsigned)min(63, max(0, (int)((cz + 1.0f) * 32.0f)));
    return (int)(expand3(bx) | (expand3(by) << 1) | (expand3(bz) << 2));
}

// ---------------------------------------------------------------------------
// Repack (stream B): tables -> feature-interleaved float2. 2 entries/thread.
// ---------------------------------------------------------------------------
__global__ void repack_kernel(const float* __restrict__ dense,
                              const float* __restrict__ hash) {
    unsigned i = blockIdx.x * blockDim.x + threadIdx.x;
    if (i < 15u * TSIZE / 2u) {
        unsigned l = i / (TSIZE / 2u);
        unsigned t = (i % (TSIZE / 2u)) * 2u;
        const float* base = hash + (size_t)l * (2u * TSIZE);
        const float2 lo = *reinterpret_cast<const float2*>(base + t);
        const float2 hi = *reinterpret_cast<const float2*>(base + TSIZE + t);
        float4 v = make_float4(lo.x, hi.x, lo.y, hi.y);
        *reinterpret_cast<float4*>(&g_hash[l * TSIZE + t]) = v;
    }
    if (i < 4096u)
        g_dense[i] = make_float2(dense[i], dense[4096u + i]);
}

// ---------------------------------------------------------------------------
// Histogram: 4 points/thread via 3x LDG.128. Resets g_total for the scan.
// ---------------------------------------------------------------------------
__global__ void hist_kernel(const float* __restrict__ coords, int N) {
    int j = blockIdx.x * blockDim.x + threadIdx.x;   // quad index
    if (j == 0) g_total = 0u;
    int p0 = j * 4;
    if (p0 >= N) return;
    if (p0 + 4 <= N) {
        const float4* c4 = reinterpret_cast<const float4*>(coords + (size_t)p0 * 3);
        const float4 a = __ldg(c4 + 0);
        const float4 b = __ldg(c4 + 1);
        const float4 c = __ldg(c4 + 2);
        atomicAdd(&g_count[bucket_of(a.x, a.y, a.z)], 1u);
        atomicAdd(&g_count[bucket_of(a.w, b.x, b.y)], 1u);
        atomicAdd(&g_count[bucket_of(b.z, b.w, c.x)], 1u);
        atomicAdd(&g_count[bucket_of(c.y, c.z, c.w)], 1u);
    } else {
        for (int p = p0; p < N; ++p) {
            int b = bucket_of(coords[3 * p], coords[3 * p + 1], coords[3 * p + 2]);
            atomicAdd(&g_count[b], 1u);
        }
    }
}

// ---------------------------------------------------------------------------
// Single-kernel scan: per-block scan + atomic global base (self-cleaning).
// ---------------------------------------------------------------------------
__global__ __launch_bounds__(1024)
void scan_kernel() {
    __shared__ unsigned sh[1024];
    __shared__ unsigned base;
    const int b = blockIdx.x, t = threadIdx.x;
    const unsigned gi = b * 1024 + t;
    const unsigned v = g_count[gi];
    g_count[gi] = 0u;                       // self-clean for next invocation
    sh[t] = v;
    __syncthreads();
    for (int off = 1; off < 1024; off <<= 1) {
        unsigned u = 0;
        if (t >= off) u = sh[t - off];
        __syncthreads();
        sh[t] += u;
        __syncthreads();
    }
    if (t == 1023) base = atomicAdd(&g_total, sh[1023]);
    __syncthreads();
    g_cursor[gi] = base + sh[t] - v;        // global exclusive prefix
}

// ---------------------------------------------------------------------------
// Scatter: 4 points/thread via 3x LDG.128.
// ---------------------------------------------------------------------------
__global__ void scatter_kernel(const float* __restrict__ coords, int N) {
    int j = blockIdx.x * blockDim.x + threadIdx.x;
    int p0 = j * 4;
    if (p0 >= N) return;
    if (p0 + 4 <= N) {
        const float4* c4 = reinterpret_cast<const float4*>(coords + (size_t)p0 * 3);
        const float4 a = __ldg(c4 + 0);
        const float4 b = __ldg(c4 + 1);
        const float4 c = __ldg(c4 + 2);
        float xs[4] = {a.x, a.w, b.z, c.y};
        float ys[4] = {a.y, b.x, b.w, c.z};
        float zs[4] = {a.z, b.y, c.x, c.w};
#pragma unroll
        for (int k = 0; k < 4; ++k) {
            int bk = bucket_of(xs[k], ys[k], zs[k]);
            unsigned slot = atomicAdd(&g_cursor[bk], 1u);
            g_buf[slot] = make_float4(xs[k], ys[k], zs[k],
                                      __int_as_float(p0 + k));
        }
    } else {
        for (int p = p0; p < N; ++p) {
            float x = coords[3 * p], y = coords[3 * p + 1], z = coords[3 * p + 2];
            int b = bucket_of(x, y, z);
            unsigned slot = atomicAdd(&g_cursor[b], 1u);
            g_buf[slot] = make_float4(x, y, z, __int_as_float(p));
        }
    }
}

// ---------------------------------------------------------------------------
// Encode: proven R11 body, Morton 64^3 bucket order, all 16 levels.
// Output stores use evict-first (__stcs): the 256MB output stream must not
// evict the 31.5MB tables + 32MB g_buf working set from L2.
// ---------------------------------------------------------------------------
__global__ __launch_bounds__(256)
void encode_kernel(float* __restrict__ out, int N) {
    int i = blockIdx.x * blockDim.x + threadIdx.x;
    if (i >= N) return;

    const float4 pt = g_buf[i];
    const float cx = pt.x, cy = pt.y, cz = pt.z;
    const int idx = __float_as_int(pt.w);

    float4* __restrict__ out4 = reinterpret_cast<float4*>(out + (size_t)idx * 32);

    constexpr int RES[NLEV] = {16, 20, 25, 32, 40, 50, 64, 80,
                               101, 128, 161, 203, 256, 322, 406, 512};

    float4 obuf = make_float4(0.f, 0.f, 0.f, 0.f);

#pragma unroll
    for (int l = 0; l < NLEV; ++l) {
        const int res = RES[l];
        const float rm1 = (float)(res - 1);

        float px = fminf(fmaxf((cx + 1.0f) * 0.5f * rm1, 0.0f), rm1);
        float py = fminf(fmaxf((cy + 1.0f) * 0.5f * rm1, 0.0f), rm1);
        float pz = fminf(fmaxf((cz + 1.0f) * 0.5f * rm1, 0.0f), rm1);

        int ix0 = (int)px;  float wx = px - (float)ix0;
        int iy0 = (int)py;  float wy = py - (float)iy0;
        int iz0 = (int)pz;  float wz = pz - (float)iz0;
        int ix1 = min(ix0 + 1, res - 1);
        int iy1 = min(iy0 + 1, res - 1);
        int iz1 = min(iz0 + 1, res - 1);

        const float wxv0 = 1.0f - wx, wxv1 = wx;
        const float wyv0 = 1.0f - wy, wyv1 = wy;
        const float wzv0 = 1.0f - wz, wzv1 = wz;

        float2 f[8];
        float  wg[8];

        if (l == 0) {
#pragma unroll
            for (int c = 0; c < 8; ++c) {
                const int xi = (c & 4) ? ix1 : ix0;
                const int yi = (c & 2) ? iy1 : iy0;
                const int zi = (c & 1) ? iz1 : iz0;
                f[c] = __ldg(&g_dense[(xi * 16 + yi) * 16 + zi]);
                wg[c] = ((c & 4) ? wxv1 : wxv0) *
                        ((c & 2) ? wyv1 : wyv0) *
                        ((c & 1) ? wzv1 : wzv0);
            }
        } else {
            const float2* __restrict__ tbl = g_hash + (size_t)(l - 1) * TSIZE;
            const unsigned hx0 = (unsigned)ix0;  // prime 1
            const unsigned hx1 = (unsigned)ix1;
            const unsigned hy0 = (unsigned)iy0 * P1;
            const unsigned hy1 = (unsigned)iy1 * P1;
            const unsigned hz0 = (unsigned)iz0 * P2;
            const unsigned hz1 = (unsigned)iz1 * P2;
#pragma unroll
            for (int c = 0; c < 8; ++c) {
                const unsigned h = (((c & 4) ? hx1 : hx0) ^
                                    ((c & 2) ? hy1 : hy0) ^
                                    ((c & 1) ? hz1 : hz0)) & TMASK;
                f[c] = __ldg(&tbl[h]);
                wg[c] = ((c & 4) ? wxv1 : wxv0) *
                        ((c & 2) ? wyv1 : wyv0) *
                        ((c & 1) ? wzv1 : wzv0);
            }
        }

        float a0 = 0.0f, a1 = 0.0f;
#pragma unroll
        for (int c = 0; c < 8; ++c) {
            a0 = fmaf(f[c].x, wg[c], a0);
            a1 = fmaf(f[c].y, wg[c], a1);
        }

        if ((l & 1) == 0) {
            obuf.x = a0; obuf.y = a1;
        } else {
            obuf.z = a0; obuf.w = a1;
            __stcs(&out4[l >> 1], obuf);    // evict-first streaming store
        }
    }
}

// ---------------------------------------------------------------------------
// kernel_launch:
//   stream 0: hist -> scan -> scatter -> encode
//   stream B: repack (independent, joins before encode)
// ---------------------------------------------------------------------------
extern "C" void kernel_launch(void* const* d_in, const int* in_sizes, int n_in,
                              void* d_out, int out_size) {
    const float* coords = (const float*)d_in[0];
    const float* dense  = (const float*)d_in[1];
    const float* hash   = (const float*)d_in[2];
    float* out = (float*)d_out;

    const int N = in_sizes[0] / 3;
    const int nb = (N + 255) / 256;
    const int nq = ((N + 3) / 4 + 255) / 256;   // quads

    static cudaStream_t s_b = nullptr;
    static cudaEvent_t ev_start = nullptr, ev_repack = nullptr;
    if (s_b == nullptr) {
        cudaStreamCreateWithFlags(&s_b, cudaStreamNonBlocking);
        cudaEventCreateWithFlags(&ev_start, cudaEventDisableTiming);
        cudaEventCreateWithFlags(&ev_repack, cudaEventDisableTiming);
    }

    cudaEventRecord(ev_start, 0);
    cudaStreamWaitEvent(s_b, ev_start, 0);
    const unsigned repack_threads = 15u * TSIZE / 2u;
    repack_kernel<<<(repack_threads + 255u) / 256u, 256, 0, s_b>>>(dense, hash);
    cudaEventRecord(ev_repack, s_b);

    hist_kernel<<<nq, 256>>>(coords, N);
    scan_kernel<<<NBUCK / 1024, 1024>>>();
    scatter_kernel<<<nq, 256>>>(coords, N);

    cudaStreamWaitEvent(0, ev_repack, 0);
    encode_kernel<<<nb, 256>>>(out, N);
}